// round 4
// baseline (speedup 1.0000x reference)
#include <cuda_runtime.h>
#include <cuda_fp16.h>
#include <mma.h>
#include <cstdint>

using namespace nvcuda;

// out[b,s,f] = scale * x[b,s,:] @ W, W = kernel ? +1 : -1
// GEMM: M=16384, K=1024, N=1024. fp16 wmma (HMMA), fp32 accum.
// Harness PTX target is compute_103 (non-'a') -> tcgen05 unavailable.
// Bool 'kernel' input element width is detected at runtime (1/2/4 bytes):
// identical rel_err=sqrt(2) across two different GEMM cores proved the bool
// array is NOT byte-packed as assumed in R2/R3.

#define M_TOTAL 16384
#define N_TOTAL 1024
#define K_TOTAL 1024

#define BM 128
#define BN 128
#define BK 32
#define STAGES 4
#define NCHUNK (K_TOTAL / BK)      // 32
#define ASTRIDE 80                 // bytes per row: 64B data + 16B pad (40 halfs)
#define A_SM_BYTES (BM * ASTRIDE)  // 10240
#define B_SM_BYTES (BN * ASTRIDE)  // 10240
#define STAGE_BYTES (A_SM_BYTES + B_SM_BYTES)   // 20480
#define SMEM_TOTAL (STAGES * STAGE_BYTES)       // 81920

__device__ __half g_xh[(size_t)M_TOTAL * K_TOTAL];   // 32 MB fp16 activations
__device__ __half g_b[(size_t)N_TOTAL * K_TOTAL];    // 2 MB, [n][k] = +/-1
__device__ int g_kwidth;                             // detected bool element width

// ---------------- helpers ----------------
__device__ __forceinline__ uint32_t smem_u32(const void* p) {
    uint32_t a;
    asm("{ .reg .u64 t; cvta.to.shared.u64 t, %1; cvt.u32.u64 %0, t; }" : "=r"(a) : "l"(p));
    return a;
}
__device__ __forceinline__ void cp_async16(uint32_t dst, const void* src) {
    asm volatile("cp.async.cg.shared.global [%0], [%1], 16;" :: "r"(dst), "l"(src) : "memory");
}

// ---------------- dtype width detection ----------------
// Scan first 4096 words. Word-packed bool (int32 0/1 or f32 0.0/1.0): words in
// {0,1,0x3F800000}. Halfword-packed (bf16/f16 0/1): halfwords in {0,1,0x3F80,0x3C00}.
// Otherwise byte-packed. Random byte-packed data defeats the word test w.p. ~(1/8)^4096.
__global__ void detect_kwidth_kernel(const uint32_t* __restrict__ kern) {
    __shared__ int not_w, not_h;
    if (threadIdx.x == 0) { not_w = 0; not_h = 0; }
    __syncthreads();
    for (int i = threadIdx.x; i < 4096; i += blockDim.x) {
        uint32_t w = kern[i];
        if (!(w == 0u || w == 1u || w == 0x3F800000u)) not_w = 1;
        uint32_t h0 = w & 0xFFFFu, h1 = w >> 16;
        bool h0ok = (h0 == 0u || h0 == 1u || h0 == 0x3F80u || h0 == 0x3C00u);
        bool h1ok = (h1 == 0u || h1 == 1u || h1 == 0x3F80u || h1 == 0x3C00u);
        if (!(h0ok && h1ok)) not_h = 1;
    }
    __syncthreads();
    if (threadIdx.x == 0)
        g_kwidth = (!not_w) ? 4 : ((!not_h) ? 2 : 1);
}

__device__ __forceinline__ bool kern_true(const void* kern, size_t idx, int width) {
    if (width == 4) return ((const uint32_t*)kern)[idx] != 0u;
    if (width == 2) return ((const uint16_t*)kern)[idx] != 0u;
    return ((const uint8_t*)kern)[idx] != 0u;
}

// ---------------- prep kernels ----------------
__global__ void convert_x_kernel(const float* __restrict__ x) {
    size_t i = (size_t)blockIdx.x * blockDim.x + threadIdx.x;   // 8 floats per thread
    size_t base = i * 8;
    float4 a = *(const float4*)(x + base);
    float4 b = *(const float4*)(x + base + 4);
    __half2 h[4];
    h[0] = __floats2half2_rn(a.x, a.y);
    h[1] = __floats2half2_rn(a.z, a.w);
    h[2] = __floats2half2_rn(b.x, b.y);
    h[3] = __floats2half2_rn(b.z, b.w);
    *(uint4*)(&g_xh[base]) = *(uint4*)h;
}

__global__ void transpose_b_kernel(const void* __restrict__ kern) {
    __shared__ unsigned char tile[32][33];
    int width = g_kwidth;
    int n0 = blockIdx.x * 32, k0 = blockIdx.y * 32;
    int tx = threadIdx.x, ty = threadIdx.y;
    #pragma unroll
    for (int r = ty; r < 32; r += 8)
        tile[r][tx] = kern_true(kern, (size_t)(k0 + r) * N_TOTAL + n0 + tx, width) ? 1 : 0;
    __syncthreads();
    const __half pos = __float2half(1.0f), neg = __float2half(-1.0f);
    #pragma unroll
    for (int r = ty; r < 32; r += 8)
        g_b[(size_t)(n0 + r) * K_TOTAL + k0 + tx] = tile[tx][r] ? pos : neg;
}

// ---------------- GEMM (wmma multistage) ----------------
__global__ __launch_bounds__(256, 2)
void gemm_kernel(const float* __restrict__ scale_ptr, float* __restrict__ out) {
    extern __shared__ __align__(16) char smem[];
    uint32_t sbase = smem_u32(smem);
    int tid = threadIdx.x;
    int wid = tid >> 5;

    int n0 = blockIdx.x * BN;
    int m0 = blockIdx.y * BM;

    // warp tile: 32(M) x 64(N); warps laid out 4(M) x 2(N)
    int wm = (wid & 3) * 32;
    int wn = (wid >> 2) * 64;

    auto load_stage = [&](int kc, int s) {
        uint32_t sA = sbase + s * STAGE_BYTES;
        uint32_t sB = sA + A_SM_BYTES;
        #pragma unroll
        for (int i = 0; i < 2; i++) {           // A: 512 x 16B chunks / 256 threads
            int c = tid + i * 256;
            int row = c >> 2, seg = c & 3;
            cp_async16(sA + row * ASTRIDE + seg * 16,
                       &g_xh[(size_t)(m0 + row) * K_TOTAL + kc + seg * 8]);
        }
        #pragma unroll
        for (int i = 0; i < 2; i++) {           // B: 512 x 16B chunks
            int c = tid + i * 256;
            int row = c >> 2, seg = c & 3;
            cp_async16(sB + row * ASTRIDE + seg * 16,
                       &g_b[(size_t)(n0 + row) * K_TOTAL + kc + seg * 8]);
        }
    };

    #pragma unroll
    for (int s = 0; s < STAGES - 1; s++) {
        load_stage(s * BK, s);
        asm volatile("cp.async.commit_group;" ::: "memory");
    }

    wmma::fragment<wmma::accumulator, 16, 16, 16, float> cf[2][4];
    #pragma unroll
    for (int mt = 0; mt < 2; mt++)
        #pragma unroll
        for (int nt = 0; nt < 4; nt++)
            wmma::fill_fragment(cf[mt][nt], 0.0f);

    for (int kc = 0; kc < NCHUNK; kc++) {
        asm volatile("cp.async.wait_group 2;" ::: "memory");
        __syncthreads();

        int pf = kc + STAGES - 1;
        if (pf < NCHUNK) load_stage(pf * BK, pf & (STAGES - 1));
        asm volatile("cp.async.commit_group;" ::: "memory");   // empty tail group keeps ids uniform

        int s = kc & (STAGES - 1);
        const char* stA = smem + s * STAGE_BYTES;
        const char* stB = stA + A_SM_BYTES;

        #pragma unroll
        for (int ks = 0; ks < 2; ks++) {       // two k16 steps per BK=32
            wmma::fragment<wmma::matrix_a, 16, 16, 16, __half, wmma::row_major> af[2];
            wmma::fragment<wmma::matrix_b, 16, 16, 16, __half, wmma::col_major> bf[4];
            #pragma unroll
            for (int mt = 0; mt < 2; mt++)
                wmma::load_matrix_sync(af[mt],
                    (const __half*)(stA + (wm + mt * 16) * ASTRIDE + ks * 32), 40);
            #pragma unroll
            for (int nt = 0; nt < 4; nt++)
                wmma::load_matrix_sync(bf[nt],
                    (const __half*)(stB + (wn + nt * 16) * ASTRIDE + ks * 32), 40);
            #pragma unroll
            for (int mt = 0; mt < 2; mt++)
                #pragma unroll
                for (int nt = 0; nt < 4; nt++)
                    wmma::mma_sync(cf[mt][nt], af[mt], bf[nt], cf[mt][nt]);
        }
    }

    // ---- epilogue: scale in-fragment, store straight to gmem ----
    float sc = *scale_ptr;
    #pragma unroll
    for (int mt = 0; mt < 2; mt++) {
        #pragma unroll
        for (int nt = 0; nt < 4; nt++) {
            #pragma unroll
            for (int e = 0; e < cf[mt][nt].num_elements; e++)
                cf[mt][nt].x[e] *= sc;
            wmma::store_matrix_sync(
                out + (size_t)(m0 + wm + mt * 16) * N_TOTAL + (n0 + wn + nt * 16),
                cf[mt][nt], N_TOTAL, wmma::mem_row_major);
        }
    }
}

// ---------------- launch ----------------
extern "C" void kernel_launch(void* const* d_in, const int* in_sizes, int n_in,
                              void* d_out, int out_size) {
    // identify inputs by element count (robust to ordering)
    const float* x = nullptr;
    const void* kern = nullptr;
    const float* scale = nullptr;
    for (int i = 0; i < n_in; i++) {
        if (in_sizes[i] == M_TOTAL * K_TOTAL) x = (const float*)d_in[i];
        else if (in_sizes[i] == K_TOTAL * N_TOTAL) kern = (const void*)d_in[i];
        else if (in_sizes[i] == 1) scale = (const float*)d_in[i];
    }
    float* out = (float*)d_out;

    cudaFuncSetAttribute(gemm_kernel, cudaFuncAttributeMaxDynamicSharedMemorySize, SMEM_TOTAL);

    detect_kwidth_kernel<<<1, 256>>>((const uint32_t*)kern);
    convert_x_kernel<<<(M_TOTAL * K_TOTAL) / (256 * 8), 256>>>(x);
    transpose_b_kernel<<<dim3(N_TOTAL / 32, K_TOTAL / 32), dim3(32, 8)>>>(kern);
    // grid.x = N tiles (adjacent CTAs share the A tile in L2), grid.y = M tiles
    gemm_kernel<<<dim3(N_TOTAL / BN, M_TOTAL / BM), 256, SMEM_TOTAL>>>(scale, out);
}